// round 1
// baseline (speedup 1.0000x reference)
#include <cuda_runtime.h>
#include <cuda_bf16.h>
#include <mma.h>
#include <math.h>

using namespace nvcuda;

// Problem constants
#define NTOKS   65536        // B*V*T*NTOK = 1*2*4*8192
#define CDIM    512
#define NGROUPS 8            // B*V*T
#define SPER    8192         // tokens per group
#define SWIN    128          // windows per group
#define NWIN    64
#define NKV     192
#define HEADS   8
#define DHEAD   64

// ---------------- device scratch (static, no runtime alloc) ----------------
__device__ __nv_bfloat16 g_q   [(size_t)NTOKS * 512];
__device__ __nv_bfloat16 g_akv [(size_t)NTOKS * 512];
__device__ __nv_bfloat16 g_kv  [(size_t)NTOKS * 1024];
__device__ __nv_bfloat16 g_attn[(size_t)NTOKS * 512];
__device__ float         g_x1  [(size_t)NTOKS * 512];
__device__ __nv_bfloat16 g_h0  [(size_t)NTOKS * 512];
__device__ __nv_bfloat16 g_h1  [(size_t)NTOKS * 1024];
// transposed bf16 weights: [Nout][K]
__device__ __nv_bfloat16 g_wkv [1024 * 512];
__device__ __nv_bfloat16 g_wo  [512 * 512];
__device__ __nv_bfloat16 g_wemb[512 * 512];
__device__ __nv_bfloat16 g_w1  [1024 * 512];
__device__ __nv_bfloat16 g_w2  [512 * 1024];

// ---------------- weight convert + transpose: dst[n][k] = src[k][n] ----------------
__global__ void conv_w_kernel(const float* __restrict__ src, __nv_bfloat16* __restrict__ dst,
                              int K, int Nout) {
    int idx = blockIdx.x * blockDim.x + threadIdx.x;
    int total = K * Nout;
    if (idx < total) {
        int n = idx / K;
        int k = idx - n * K;
        dst[idx] = __float2bfloat16(src[k * Nout + n]);
    }
}

// ---------------- LayerNorm (optionally dual-output) ----------------
// One block per token row (512 floats). 128 threads, float4 each.
__global__ void __launch_bounds__(128)
ln_kernel(const float* __restrict__ x,
          const float* __restrict__ g1, const float* __restrict__ b1, __nv_bfloat16* __restrict__ o1,
          const float* __restrict__ g2, const float* __restrict__ b2, __nv_bfloat16* __restrict__ o2) {
    size_t t = blockIdx.x;
    int tid = threadIdx.x;
    float4 v = ((const float4*)(x + t * 512))[tid];
    float s = v.x + v.y + v.z + v.w;
    float q = v.x*v.x + v.y*v.y + v.z*v.z + v.w*v.w;
    for (int o = 16; o; o >>= 1) {
        s += __shfl_xor_sync(0xffffffffu, s, o);
        q += __shfl_xor_sync(0xffffffffu, q, o);
    }
    __shared__ float ss[4], sq[4];
    if ((tid & 31) == 0) { ss[tid >> 5] = s; sq[tid >> 5] = q; }
    __syncthreads();
    s = ss[0] + ss[1] + ss[2] + ss[3];
    q = sq[0] + sq[1] + sq[2] + sq[3];
    float mean = s * (1.0f / 512.0f);
    float var  = q * (1.0f / 512.0f) - mean * mean;
    float rstd = rsqrtf(var + 1e-5f);

    int c = tid * 4;
    float xh0 = (v.x - mean) * rstd;
    float xh1 = (v.y - mean) * rstd;
    float xh2 = (v.z - mean) * rstd;
    float xh3 = (v.w - mean) * rstd;

    {
        float y0 = xh0 * g1[c]   + b1[c];
        float y1 = xh1 * g1[c+1] + b1[c+1];
        float y2 = xh2 * g1[c+2] + b1[c+2];
        float y3 = xh3 * g1[c+3] + b1[c+3];
        __nv_bfloat162* p = (__nv_bfloat162*)(o1 + t * 512 + c);
        p[0] = __floats2bfloat162_rn(y0, y1);
        p[1] = __floats2bfloat162_rn(y2, y3);
    }
    if (o2) {
        float y0 = xh0 * g2[c]   + b2[c];
        float y1 = xh1 * g2[c+1] + b2[c+1];
        float y2 = xh2 * g2[c+2] + b2[c+2];
        float y3 = xh3 * g2[c+3] + b2[c+3];
        __nv_bfloat162* p = (__nv_bfloat162*)(o2 + t * 512 + c);
        p[0] = __floats2bfloat162_rn(y0, y1);
        p[1] = __floats2bfloat162_rn(y2, y3);
    }
}

// ---------------- bf16 WMMA GEMM: C[M,Nout] = A[M,K] @ Bt[Nout,K]^T + epilogue ----------------
enum { EPI_BIAS_BF16 = 0, EPI_GELU_BF16 = 1, EPI_RESID_F32 = 2 };

#define BM 128
#define BN 64
#define BK 64
#define LDA 72   // bf16 smem leading dim (pad 8)
#define LDC 68   // f32 smem C leading dim (pad 4)

template<int K, int EPI>
__global__ void __launch_bounds__(256)
gemm_bf16(const __nv_bfloat16* __restrict__ A,
          const __nv_bfloat16* __restrict__ Bt,
          const float* __restrict__ bias,
          __nv_bfloat16* __restrict__ outB,
          float* __restrict__ outF,
          const float* __restrict__ resid,
          const float* __restrict__ scale,
          int Nout) {
    __shared__ __align__(16) unsigned char smem_raw[BM * LDC * 4];  // 34816 B, reused
    __nv_bfloat16* sA = (__nv_bfloat16*)smem_raw;
    __nv_bfloat16* sB = sA + BM * LDA;
    float* sC = (float*)smem_raw;

    int tid  = threadIdx.x;
    int warp = tid >> 5;
    int wm = warp & 3;      // 4 warps along M (32 rows each)
    int wn = warp >> 2;     // 2 warps along N (32 cols each)
    int mbase = blockIdx.y * BM;
    int nbase = blockIdx.x * BN;

    wmma::fragment<wmma::accumulator, 16, 16, 16, float> acc[2][2];
    #pragma unroll
    for (int i = 0; i < 2; i++)
        #pragma unroll
        for (int j = 0; j < 2; j++)
            wmma::fill_fragment(acc[i][j], 0.0f);

    for (int kt = 0; kt < K; kt += BK) {
        // A tile: 128 x 64 bf16 => 1024 chunks of 16B, 4 per thread
        #pragma unroll
        for (int it = 0; it < 4; it++) {
            int ch = tid + it * 256;
            int r = ch >> 3, cc = (ch & 7) << 3;
            *(uint4*)(sA + r * LDA + cc) =
                *(const uint4*)(A + (size_t)(mbase + r) * K + kt + cc);
        }
        // B tile: 64 x 64 bf16 => 512 chunks, 2 per thread
        #pragma unroll
        for (int it = 0; it < 2; it++) {
            int ch = tid + it * 256;
            int r = ch >> 3, cc = (ch & 7) << 3;
            *(uint4*)(sB + r * LDA + cc) =
                *(const uint4*)(Bt + (size_t)(nbase + r) * K + kt + cc);
        }
        __syncthreads();
        #pragma unroll
        for (int ks = 0; ks < BK; ks += 16) {
            wmma::fragment<wmma::matrix_a, 16, 16, 16, __nv_bfloat16, wmma::row_major> af[2];
            wmma::fragment<wmma::matrix_b, 16, 16, 16, __nv_bfloat16, wmma::col_major> bf[2];
            wmma::load_matrix_sync(af[0], sA + (wm * 32)      * LDA + ks, LDA);
            wmma::load_matrix_sync(af[1], sA + (wm * 32 + 16) * LDA + ks, LDA);
            wmma::load_matrix_sync(bf[0], sB + (wn * 32)      * LDA + ks, LDA);
            wmma::load_matrix_sync(bf[1], sB + (wn * 32 + 16) * LDA + ks, LDA);
            #pragma unroll
            for (int i = 0; i < 2; i++)
                #pragma unroll
                for (int j = 0; j < 2; j++)
                    wmma::mma_sync(acc[i][j], af[i], bf[j], acc[i][j]);
        }
        __syncthreads();
    }

    // stage C in smem
    #pragma unroll
    for (int i = 0; i < 2; i++)
        #pragma unroll
        for (int j = 0; j < 2; j++)
            wmma::store_matrix_sync(sC + (wm * 32 + i * 16) * LDC + wn * 32 + j * 16,
                                    acc[i][j], LDC, wmma::mem_row_major);
    __syncthreads();

    // epilogue
    for (int e = tid; e < BM * BN; e += 256) {
        int r = e >> 6;          // BN == 64
        int c = e & 63;
        float v = sC[r * LDC + c];
        int gr = mbase + r;
        int gc = nbase + c;
        float bz = bias[gc];
        if (EPI == EPI_BIAS_BF16) {
            outB[(size_t)gr * Nout + gc] = __float2bfloat16(v + bz);
        } else if (EPI == EPI_GELU_BF16) {
            float t = v + bz;
            float gl = 0.5f * t * (1.0f + tanhf(0.7978845608028654f * (t + 0.044715f * t * t * t)));
            outB[(size_t)gr * Nout + gc] = __float2bfloat16(gl);
        } else { // EPI_RESID_F32
            float t = v + bz;
            outF[(size_t)gr * Nout + gc] = resid[(size_t)gr * Nout + gc] + scale[gc] * t;
        }
    }
}

// ---------------- windowed attention: one block per (window, head) ----------------
#define LDQ 72    // bf16 Q/K/V leading dim
#define LDS 200   // S/P leading dim

// dynamic smem layout (bytes):
//  sQ : 64*72*2   =  9216
//  sK : 192*72*2  = 27648
//  sV : 192*72*2  = 27648    (starts at 36864)
//  sS : 64*200*4  = 51200    (starts at 64512)
//  sP : 64*200*2  = 25600    overlays sQ+sK region
//  sO : 64*72*4   = 18432    overlays sS region
#define ATTN_SMEM (9216 + 27648 + 27648 + 51200)

__global__ void __launch_bounds__(256)
attn_kernel(const __nv_bfloat16* __restrict__ q,
            const __nv_bfloat16* __restrict__ kv,
            __nv_bfloat16* __restrict__ attn_out) {
    extern __shared__ __align__(16) unsigned char dsm[];
    __nv_bfloat16* sQ = (__nv_bfloat16*)dsm;
    __nv_bfloat16* sK = sQ + 64 * LDQ;
    __nv_bfloat16* sV = sK + NKV * LDQ;
    float*         sS = (float*)(dsm + 64512);
    __nv_bfloat16* sP = (__nv_bfloat16*)dsm;   // overlay
    float*         sO = sS;                    // overlay

    int bid  = blockIdx.x;
    int head = bid & 7;
    int win  = bid >> 3;
    int g    = win >> 7;
    int sw   = win & 127;
    size_t tbase = (size_t)g * SPER + (size_t)sw * NWIN;

    int tid  = threadIdx.x;
    int warp = tid >> 5;
    bool valid0 = (sw > 0);
    bool valid2 = (sw < SWIN - 1);
    int cl0 = valid0 ? (sw - 1) : 0;
    int cl2 = valid2 ? (sw + 1) : (SWIN - 1);
    size_t kb0 = (size_t)g * SPER + (size_t)cl0 * NWIN;
    size_t kb2 = (size_t)g * SPER + (size_t)cl2 * NWIN;

    // load Q: 64 rows x 64 cols => 512 16B-chunks
    #pragma unroll
    for (int it = 0; it < 2; it++) {
        int ch = tid + it * 256;
        int r = ch >> 3, cc = (ch & 7) << 3;
        *(uint4*)(sQ + r * LDQ + cc) =
            *(const uint4*)(q + (tbase + r) * 512 + head * 64 + cc);
    }
    // load K,V: 192 rows x 64 cols each => 1536 chunks each
    #pragma unroll
    for (int it = 0; it < 6; it++) {
        int ch = tid + it * 256;
        int r = ch >> 3, cc = (ch & 7) << 3;
        int nb = r >> 6, lr = r & 63;
        size_t tok = (nb == 0 ? kb0 : (nb == 1 ? tbase : kb2)) + lr;
        *(uint4*)(sK + r * LDQ + cc) = *(const uint4*)(kv + tok * 1024 + head * 64 + cc);
        *(uint4*)(sV + r * LDQ + cc) = *(const uint4*)(kv + tok * 1024 + 512 + head * 64 + cc);
    }
    __syncthreads();

    // S = (Q @ K^T) / 8 : 64x192 fp32
    {
        int r0 = (warp & 3) * 16;
        int c0 = (warp >> 2) * 96;
        wmma::fragment<wmma::matrix_a, 16, 16, 16, __nv_bfloat16, wmma::row_major> af[4];
        #pragma unroll
        for (int kk = 0; kk < 4; kk++)
            wmma::load_matrix_sync(af[kk], sQ + r0 * LDQ + kk * 16, LDQ);
        #pragma unroll
        for (int j = 0; j < 6; j++) {
            wmma::fragment<wmma::accumulator, 16, 16, 16, float> acc;
            wmma::fill_fragment(acc, 0.0f);
            #pragma unroll
            for (int kk = 0; kk < 4; kk++) {
                wmma::fragment<wmma::matrix_b, 16, 16, 16, __nv_bfloat16, wmma::col_major> bfr;
                wmma::load_matrix_sync(bfr, sK + (c0 + j * 16) * LDQ + kk * 16, LDQ);
                wmma::mma_sync(acc, af[kk], bfr, acc);
            }
            #pragma unroll
            for (int t2 = 0; t2 < acc.num_elements; t2++) acc.x[t2] *= 0.125f;
            wmma::store_matrix_sync(sS + r0 * LDS + c0 + j * 16, acc, LDS, wmma::mem_row_major);
        }
    }
    __syncthreads();

    // masked softmax over each of 64 rows (192 cols); write P (bf16) to sP
    if (tid < 64) {
        float* srow = sS + tid * LDS;
        int lo = valid0 ? 0   : 64;
        int hi = valid2 ? 192 : 128;
        float mx = -3.0e38f;
        for (int c = lo; c < hi; c++) mx = fmaxf(mx, srow[c]);
        float sum = 0.0f;
        for (int c = lo; c < hi; c++) { float e = __expf(srow[c] - mx); srow[c] = e; sum += e; }
        float inv = 1.0f / sum;
        __nv_bfloat16* prow = sP + tid * LDS;
        for (int c = 0; c < 192; c++) {
            float p = (c >= lo && c < hi) ? srow[c] * inv : 0.0f;
            prow[c] = __float2bfloat16(p);
        }
    }
    __syncthreads();

    // O = P @ V : 64x64
    {
        int r0 = (warp & 3) * 16;
        int c0 = (warp >> 2) * 32;
        #pragma unroll
        for (int j = 0; j < 2; j++) {
            wmma::fragment<wmma::accumulator, 16, 16, 16, float> acc;
            wmma::fill_fragment(acc, 0.0f);
            #pragma unroll
            for (int kk = 0; kk < 12; kk++) {
                wmma::fragment<wmma::matrix_a, 16, 16, 16, __nv_bfloat16, wmma::row_major> afr;
                wmma::fragment<wmma::matrix_b, 16, 16, 16, __nv_bfloat16, wmma::row_major> bfr;
                wmma::load_matrix_sync(afr, sP + r0 * LDS + kk * 16, LDS);
                wmma::load_matrix_sync(bfr, sV + (kk * 16) * LDQ + c0 + j * 16, LDQ);
                wmma::mma_sync(acc, afr, bfr, acc);
            }
            wmma::store_matrix_sync(sO + r0 * LDQ + c0 + j * 16, acc, LDQ, wmma::mem_row_major);
        }
    }
    __syncthreads();

    for (int e = tid; e < 64 * 64; e += 256) {
        int r = e >> 6, c = e & 63;
        attn_out[(tbase + r) * 512 + head * 64 + c] = __float2bfloat16(sO[r * LDQ + c]);
    }
}

// ---------------- host launcher ----------------
extern "C" void kernel_launch(void* const* d_in, const int* in_sizes, int n_in,
                              void* d_out, int out_size) {
    (void)in_sizes; (void)n_in; (void)out_size;
    const float* x       = (const float*)d_in[0];
    const float* ln_q_g  = (const float*)d_in[1];
    const float* ln_q_b  = (const float*)d_in[2];
    const float* ln_kv_g = (const float*)d_in[3];
    const float* ln_kv_b = (const float*)d_in[4];
    const float* W_kv    = (const float*)d_in[5];
    const float* b_kv    = (const float*)d_in[6];
    const float* W_o     = (const float*)d_in[7];
    const float* b_o     = (const float*)d_in[8];
    const float* gamma   = (const float*)d_in[9];
    const float* ln_m_g  = (const float*)d_in[10];
    const float* ln_m_b  = (const float*)d_in[11];
    const float* W_emb   = (const float*)d_in[12];
    const float* b_emb   = (const float*)d_in[13];
    const float* W1      = (const float*)d_in[14];
    const float* b1      = (const float*)d_in[15];
    const float* W2      = (const float*)d_in[16];
    const float* b2      = (const float*)d_in[17];
    const float* gamma_mlp = (const float*)d_in[18];
    float* out = (float*)d_out;

    void *p_q, *p_akv, *p_kv, *p_attn, *p_x1, *p_h0, *p_h1;
    void *p_wkv, *p_wo, *p_wemb, *p_w1, *p_w2;
    cudaGetSymbolAddress(&p_q,    g_q);
    cudaGetSymbolAddress(&p_akv,  g_akv);
    cudaGetSymbolAddress(&p_kv,   g_kv);
    cudaGetSymbolAddress(&p_attn, g_attn);
    cudaGetSymbolAddress(&p_x1,   g_x1);
    cudaGetSymbolAddress(&p_h0,   g_h0);
    cudaGetSymbolAddress(&p_h1,   g_h1);
    cudaGetSymbolAddress(&p_wkv,  g_wkv);
    cudaGetSymbolAddress(&p_wo,   g_wo);
    cudaGetSymbolAddress(&p_wemb, g_wemb);
    cudaGetSymbolAddress(&p_w1,   g_w1);
    cudaGetSymbolAddress(&p_w2,   g_w2);

    cudaFuncSetAttribute(attn_kernel, cudaFuncAttributeMaxDynamicSharedMemorySize, ATTN_SMEM);

    // 0) weight convert+transpose (bf16, [Nout][K])
    conv_w_kernel<<<(512 * 1024 + 255) / 256, 256>>>(W_kv,  (__nv_bfloat16*)p_wkv,  512, 1024);
    conv_w_kernel<<<(512 * 512  + 255) / 256, 256>>>(W_o,   (__nv_bfloat16*)p_wo,   512, 512);
    conv_w_kernel<<<(512 * 512  + 255) / 256, 256>>>(W_emb, (__nv_bfloat16*)p_wemb, 512, 512);
    conv_w_kernel<<<(512 * 1024 + 255) / 256, 256>>>(W1,    (__nv_bfloat16*)p_w1,   512, 1024);
    conv_w_kernel<<<(1024 * 512 + 255) / 256, 256>>>(W2,    (__nv_bfloat16*)p_w2,  1024, 512);

    // 1) dual LN: q = LN_q(x), akv = LN_kv(x)
    ln_kernel<<<NTOKS, 128>>>(x, ln_q_g, ln_q_b, (__nv_bfloat16*)p_q,
                                 ln_kv_g, ln_kv_b, (__nv_bfloat16*)p_akv);

    // 2) kv = akv @ W_kv + b_kv   [65536 x 1024]
    gemm_bf16<512, EPI_BIAS_BF16><<<dim3(1024 / BN, NTOKS / BM), 256>>>(
        (const __nv_bfloat16*)p_akv, (const __nv_bfloat16*)p_wkv, b_kv,
        (__nv_bfloat16*)p_kv, nullptr, nullptr, nullptr, 1024);

    // 3) windowed attention -> g_attn [65536 x 512]
    attn_kernel<<<NGROUPS * SWIN * HEADS, 256, ATTN_SMEM>>>(
        (const __nv_bfloat16*)p_q, (const __nv_bfloat16*)p_kv, (__nv_bfloat16*)p_attn);

    // 4) x1 = x + gamma * (attn @ W_o + b_o)
    gemm_bf16<512, EPI_RESID_F32><<<dim3(512 / BN, NTOKS / BM), 256>>>(
        (const __nv_bfloat16*)p_attn, (const __nv_bfloat16*)p_wo, b_o,
        nullptr, (float*)p_x1, x, gamma, 512);

    // 5) aemb = LN_m(x1)  (reuse g_akv)
    ln_kernel<<<NTOKS, 128>>>((const float*)p_x1, ln_m_g, ln_m_b, (__nv_bfloat16*)p_akv,
                              nullptr, nullptr, nullptr);

    // 6) h0 = aemb @ W_emb + b_emb
    gemm_bf16<512, EPI_BIAS_BF16><<<dim3(512 / BN, NTOKS / BM), 256>>>(
        (const __nv_bfloat16*)p_akv, (const __nv_bfloat16*)p_wemb, b_emb,
        (__nv_bfloat16*)p_h0, nullptr, nullptr, nullptr, 512);

    // 7) h1 = gelu(h0 @ W1 + b1)   [65536 x 1024]
    gemm_bf16<512, EPI_GELU_BF16><<<dim3(1024 / BN, NTOKS / BM), 256>>>(
        (const __nv_bfloat16*)p_h0, (const __nv_bfloat16*)p_w1, b1,
        (__nv_bfloat16*)p_h1, nullptr, nullptr, nullptr, 1024);

    // 8) out = x1 + gamma_mlp * (h1 @ W2 + b2)
    gemm_bf16<1024, EPI_RESID_F32><<<dim3(512 / BN, NTOKS / BM), 256>>>(
        (const __nv_bfloat16*)p_h1, (const __nv_bfloat16*)p_w2, b2,
        nullptr, out, (const float*)p_x1, gamma_mlp, 512);
}

// round 2
// speedup vs baseline: 1.2088x; 1.2088x over previous
#include <cuda_runtime.h>
#include <cuda_bf16.h>
#include <mma.h>
#include <math.h>

using namespace nvcuda;

// Problem constants
#define NTOKS   65536
#define CDIM    512
#define NGROUPS 8
#define SPER    8192
#define SWIN    128
#define NWIN    64
#define NKV     192
#define HEADS   8
#define DHEAD   64

// ---------------- device scratch ----------------
__device__ __nv_bfloat16 g_q   [(size_t)NTOKS * 512];
__device__ __nv_bfloat16 g_akv [(size_t)NTOKS * 512];
__device__ __nv_bfloat16 g_kv  [(size_t)NTOKS * 1024];
__device__ __nv_bfloat16 g_attn[(size_t)NTOKS * 512];
__device__ float         g_x1  [(size_t)NTOKS * 512];
__device__ __nv_bfloat16 g_h0  [(size_t)NTOKS * 512];
__device__ __nv_bfloat16 g_h1  [(size_t)NTOKS * 1024];
__device__ __nv_bfloat16 g_wkv [1024 * 512];
__device__ __nv_bfloat16 g_wo  [512 * 512];
__device__ __nv_bfloat16 g_wemb[512 * 512];
__device__ __nv_bfloat16 g_w1  [1024 * 512];
__device__ __nv_bfloat16 g_w2  [512 * 1024];

// ---------------- cp.async helpers ----------------
__device__ __forceinline__ void cp16(void* dst, const void* src) {
    unsigned d = (unsigned)__cvta_generic_to_shared(dst);
    asm volatile("cp.async.cg.shared.global [%0], [%1], 16;\n" :: "r"(d), "l"(src));
}
__device__ __forceinline__ void cp_commit() { asm volatile("cp.async.commit_group;\n"); }
template<int N> __device__ __forceinline__ void cp_wait() {
    asm volatile("cp.async.wait_group %0;\n" :: "n"(N));
}

// ---------------- fused weight convert+transpose ----------------
// dst[n][k] = bf16(src[k][n]); 5 segments selected by blockIdx.y
__global__ void conv_w_all(const float* s0, __nv_bfloat16* d0,   // W_kv  512x1024
                           const float* s1, __nv_bfloat16* d1,   // W_o   512x512
                           const float* s2, __nv_bfloat16* d2,   // W_emb 512x512
                           const float* s3, __nv_bfloat16* d3,   // W1    512x1024
                           const float* s4, __nv_bfloat16* d4) { // W2   1024x512
    int idx = blockIdx.x * blockDim.x + threadIdx.x;
    const float* src; __nv_bfloat16* dst; int K, Nout;
    switch (blockIdx.y) {
        case 0: src = s0; dst = d0; K = 512;  Nout = 1024; break;
        case 1: src = s1; dst = d1; K = 512;  Nout = 512;  break;
        case 2: src = s2; dst = d2; K = 512;  Nout = 512;  break;
        case 3: src = s3; dst = d3; K = 512;  Nout = 1024; break;
        default:src = s4; dst = d4; K = 1024; Nout = 512;  break;
    }
    if (idx < K * Nout) {
        int n = idx / K;
        int k = idx - n * K;
        dst[idx] = __float2bfloat16(src[k * Nout + n]);
    }
}

// ---------------- LayerNorm (optionally dual-output) ----------------
__global__ void __launch_bounds__(128)
ln_kernel(const float* __restrict__ x,
          const float* __restrict__ g1, const float* __restrict__ b1, __nv_bfloat16* __restrict__ o1,
          const float* __restrict__ g2, const float* __restrict__ b2, __nv_bfloat16* __restrict__ o2) {
    size_t t = blockIdx.x;
    int tid = threadIdx.x;
    float4 v = ((const float4*)(x + t * 512))[tid];
    float s = v.x + v.y + v.z + v.w;
    float q = v.x*v.x + v.y*v.y + v.z*v.z + v.w*v.w;
    for (int o = 16; o; o >>= 1) {
        s += __shfl_xor_sync(0xffffffffu, s, o);
        q += __shfl_xor_sync(0xffffffffu, q, o);
    }
    __shared__ float ss[4], sq[4];
    if ((tid & 31) == 0) { ss[tid >> 5] = s; sq[tid >> 5] = q; }
    __syncthreads();
    s = ss[0] + ss[1] + ss[2] + ss[3];
    q = sq[0] + sq[1] + sq[2] + sq[3];
    float mean = s * (1.0f / 512.0f);
    float var  = q * (1.0f / 512.0f) - mean * mean;
    float rstd = rsqrtf(var + 1e-5f);

    int c = tid * 4;
    float xh0 = (v.x - mean) * rstd;
    float xh1 = (v.y - mean) * rstd;
    float xh2 = (v.z - mean) * rstd;
    float xh3 = (v.w - mean) * rstd;
    {
        float y0 = xh0 * g1[c]   + b1[c];
        float y1 = xh1 * g1[c+1] + b1[c+1];
        float y2 = xh2 * g1[c+2] + b1[c+2];
        float y3 = xh3 * g1[c+3] + b1[c+3];
        __nv_bfloat162* p = (__nv_bfloat162*)(o1 + t * 512 + c);
        p[0] = __floats2bfloat162_rn(y0, y1);
        p[1] = __floats2bfloat162_rn(y2, y3);
    }
    if (o2) {
        float y0 = xh0 * g2[c]   + b2[c];
        float y1 = xh1 * g2[c+1] + b2[c+1];
        float y2 = xh2 * g2[c+2] + b2[c+2];
        float y3 = xh3 * g2[c+3] + b2[c+3];
        __nv_bfloat162* p = (__nv_bfloat162*)(o2 + t * 512 + c);
        p[0] = __floats2bfloat162_rn(y0, y1);
        p[1] = __floats2bfloat162_rn(y2, y3);
    }
}

// ---------------- double-buffered WMMA GEMM: 128x128x64 tiles ----------------
enum { EPI_BIAS_BF16 = 0, EPI_GELU_BF16 = 1, EPI_RESID_F32 = 2 };

#define BM2 128
#define BN2 128
#define BK2 64
#define LDT 72          // bf16 smem leading dim
#define TILE_B (BM2 * LDT * 2)   // 18432 bytes per tile buffer
#define LDC2 132        // f32 smem C leading dim
#define GEMM_SMEM (4 * TILE_B)   // 73728 bytes

template<int K, int EPI>
__global__ void __launch_bounds__(256)
gemm2(const __nv_bfloat16* __restrict__ A,
      const __nv_bfloat16* __restrict__ Bt,
      const float* __restrict__ bias,
      __nv_bfloat16* __restrict__ outB,
      float* __restrict__ outF,
      const float* __restrict__ resid,
      const float* __restrict__ scale,
      int Nout) {
    extern __shared__ __align__(16) unsigned char dsm[];
    __nv_bfloat16* sA[2] = {(__nv_bfloat16*)dsm, (__nv_bfloat16*)(dsm + TILE_B)};
    __nv_bfloat16* sB[2] = {(__nv_bfloat16*)(dsm + 2*TILE_B), (__nv_bfloat16*)(dsm + 3*TILE_B)};
    float* sC = (float*)dsm;

    int tid  = threadIdx.x;
    int warp = tid >> 5;
    int wm = warp & 3;      // 4 warps along M (32 rows each)
    int wn = warp >> 2;     // 2 warps along N (64 cols each)
    int mbase = blockIdx.y * BM2;
    int nbase = blockIdx.x * BN2;

    // per-thread chunk coords (shared by A and B loads): 1024 chunks/tile, 4/thread
    int r0c[4], c0c[4];
    #pragma unroll
    for (int it = 0; it < 4; it++) {
        int ch = tid + it * 256;
        r0c[it] = ch >> 3;
        c0c[it] = (ch & 7) << 3;
    }

    wmma::fragment<wmma::accumulator, 16, 16, 16, float> acc[2][4];
    #pragma unroll
    for (int i = 0; i < 2; i++)
        #pragma unroll
        for (int j = 0; j < 4; j++)
            wmma::fill_fragment(acc[i][j], 0.0f);

    constexpr int KT = K / BK2;

    // prologue: stage tiles 0 and 1
    #pragma unroll
    for (int p = 0; p < 2; p++) {
        #pragma unroll
        for (int it = 0; it < 4; it++)
            cp16(sA[p] + r0c[it] * LDT + c0c[it],
                 A + (size_t)(mbase + r0c[it]) * K + p * BK2 + c0c[it]);
        #pragma unroll
        for (int it = 0; it < 4; it++)
            cp16(sB[p] + r0c[it] * LDT + c0c[it],
                 Bt + (size_t)(nbase + r0c[it]) * K + p * BK2 + c0c[it]);
        cp_commit();
    }

    for (int kt = 0; kt < KT; kt++) {
        if (kt == KT - 1) cp_wait<0>(); else cp_wait<1>();
        __syncthreads();
        int b = kt & 1;
        #pragma unroll
        for (int ks = 0; ks < BK2; ks += 16) {
            wmma::fragment<wmma::matrix_a, 16, 16, 16, __nv_bfloat16, wmma::row_major> af[2];
            wmma::fragment<wmma::matrix_b, 16, 16, 16, __nv_bfloat16, wmma::col_major> bf[4];
            wmma::load_matrix_sync(af[0], sA[b] + (wm * 32)      * LDT + ks, LDT);
            wmma::load_matrix_sync(af[1], sA[b] + (wm * 32 + 16) * LDT + ks, LDT);
            #pragma unroll
            for (int j = 0; j < 4; j++)
                wmma::load_matrix_sync(bf[j], sB[b] + (wn * 64 + j * 16) * LDT + ks, LDT);
            #pragma unroll
            for (int i = 0; i < 2; i++)
                #pragma unroll
                for (int j = 0; j < 4; j++)
                    wmma::mma_sync(acc[i][j], af[i], bf[j], acc[i][j]);
        }
        __syncthreads();
        if (kt + 2 < KT) {
            #pragma unroll
            for (int it = 0; it < 4; it++)
                cp16(sA[b] + r0c[it] * LDT + c0c[it],
                     A + (size_t)(mbase + r0c[it]) * K + (kt + 2) * BK2 + c0c[it]);
            #pragma unroll
            for (int it = 0; it < 4; it++)
                cp16(sB[b] + r0c[it] * LDT + c0c[it],
                     Bt + (size_t)(nbase + r0c[it]) * K + (kt + 2) * BK2 + c0c[it]);
            cp_commit();
        }
    }

    // stage C in smem (overlay)
    #pragma unroll
    for (int i = 0; i < 2; i++)
        #pragma unroll
        for (int j = 0; j < 4; j++)
            wmma::store_matrix_sync(sC + (wm * 32 + i * 16) * LDC2 + wn * 64 + j * 16,
                                    acc[i][j], LDC2, wmma::mem_row_major);
    __syncthreads();

    // epilogue: 16384 elements / 256 threads = 64 each
    #pragma unroll 4
    for (int e = tid; e < BM2 * BN2; e += 256) {
        int r = e >> 7;
        int c = e & 127;
        float v = sC[r * LDC2 + c];
        int gr = mbase + r;
        int gc = nbase + c;
        float bz = bias[gc];
        if (EPI == EPI_BIAS_BF16) {
            outB[(size_t)gr * Nout + gc] = __float2bfloat16(v + bz);
        } else if (EPI == EPI_GELU_BF16) {
            float t = v + bz;
            float u = 0.7978845608028654f * (t + 0.044715f * t * t * t);
            float th;
            asm("tanh.approx.f32 %0, %1;" : "=f"(th) : "f"(u));
            outB[(size_t)gr * Nout + gc] = __float2bfloat16(0.5f * t * (1.0f + th));
        } else {
            float t = v + bz;
            outF[(size_t)gr * Nout + gc] = resid[(size_t)gr * Nout + gc] + scale[gc] * t;
        }
    }
}

// ---------------- windowed attention ----------------
#define LDQ 72     // bf16 Q/K/V smem ld
#define LDS_S 196  // fp32 S ld (mult of 4)
#define LDS_P 200  // bf16 P ld (mult of 8)

// smem layout (bytes):
//  sQ : 64*72*2   =  9216   @ 0
//  sK : 192*72*2  = 27648   @ 9216
//  sV : 192*72*2  = 27648   @ 36864
//  sS : 64*196*4  = 50176   @ 64512
//  sP : 64*200*2  = 25600   overlays sQ+sK  @ 0
//  sO : 64*72*4   = 18432   overlays sS     @ 64512
#define ATTN_SMEM (9216 + 27648 + 27648 + 50176)   // 114688 = 112 KB -> 2 blocks/SM

__global__ void __launch_bounds__(256)
attn_kernel(const __nv_bfloat16* __restrict__ q,
            const __nv_bfloat16* __restrict__ kv,
            __nv_bfloat16* __restrict__ attn_out) {
    extern __shared__ __align__(16) unsigned char dsm[];
    __nv_bfloat16* sQ = (__nv_bfloat16*)dsm;
    __nv_bfloat16* sK = sQ + 64 * LDQ;
    __nv_bfloat16* sV = sK + NKV * LDQ;
    float*         sS = (float*)(dsm + 64512);
    __nv_bfloat16* sP = (__nv_bfloat16*)dsm;
    float*         sO = sS;

    int bid  = blockIdx.x;
    int head = bid & 7;
    int win  = bid >> 3;
    int g    = win >> 7;
    int sw   = win & 127;
    size_t tbase = (size_t)g * SPER + (size_t)sw * NWIN;

    int tid  = threadIdx.x;
    int warp = tid >> 5;
    bool valid0 = (sw > 0);
    bool valid2 = (sw < SWIN - 1);
    int cl0 = valid0 ? (sw - 1) : 0;
    int cl2 = valid2 ? (sw + 1) : (SWIN - 1);
    size_t kb0 = (size_t)g * SPER + (size_t)cl0 * NWIN;
    size_t kb2 = (size_t)g * SPER + (size_t)cl2 * NWIN;

    // async loads: Q (2 chunks/thread), K & V (6 chunks/thread each)
    #pragma unroll
    for (int it = 0; it < 2; it++) {
        int ch = tid + it * 256;
        int r = ch >> 3, cc = (ch & 7) << 3;
        cp16(sQ + r * LDQ + cc, q + (tbase + r) * 512 + head * 64 + cc);
    }
    #pragma unroll
    for (int it = 0; it < 6; it++) {
        int ch = tid + it * 256;
        int r = ch >> 3, cc = (ch & 7) << 3;
        int nb = r >> 6, lr = r & 63;
        size_t tok = (nb == 0 ? kb0 : (nb == 1 ? tbase : kb2)) + lr;
        cp16(sK + r * LDQ + cc, kv + tok * 1024 + head * 64 + cc);
        cp16(sV + r * LDQ + cc, kv + tok * 1024 + 512 + head * 64 + cc);
    }
    cp_commit();
    cp_wait<0>();
    __syncthreads();

    // S = (Q @ K^T) / 8 : 64x192 fp32
    {
        int r0 = (warp & 3) * 16;
        int c0 = (warp >> 2) * 96;
        wmma::fragment<wmma::matrix_a, 16, 16, 16, __nv_bfloat16, wmma::row_major> af[4];
        #pragma unroll
        for (int kk = 0; kk < 4; kk++)
            wmma::load_matrix_sync(af[kk], sQ + r0 * LDQ + kk * 16, LDQ);
        #pragma unroll
        for (int j = 0; j < 6; j++) {
            wmma::fragment<wmma::accumulator, 16, 16, 16, float> acc;
            wmma::fill_fragment(acc, 0.0f);
            #pragma unroll
            for (int kk = 0; kk < 4; kk++) {
                wmma::fragment<wmma::matrix_b, 16, 16, 16, __nv_bfloat16, wmma::col_major> bfr;
                wmma::load_matrix_sync(bfr, sK + (c0 + j * 16) * LDQ + kk * 16, LDQ);
                wmma::mma_sync(acc, af[kk], bfr, acc);
            }
            #pragma unroll
            for (int t2 = 0; t2 < acc.num_elements; t2++) acc.x[t2] *= 0.125f;
            wmma::store_matrix_sync(sS + r0 * LDS_S + c0 + j * 16, acc, LDS_S, wmma::mem_row_major);
        }
    }
    __syncthreads();

    // masked softmax: 4 threads per row, 48 cols each
    {
        int r  = tid >> 2;
        int l4 = tid & 3;
        float* srow = sS + r * LDS_S;
        int lo = valid0 ? 0   : 64;
        int hi = valid2 ? 192 : 128;
        int cb = l4 * 48;
        float mx = -3.0e38f;
        #pragma unroll 8
        for (int c = cb; c < cb + 48; c++)
            if (c >= lo && c < hi) mx = fmaxf(mx, srow[c]);
        mx = fmaxf(mx, __shfl_xor_sync(0xffffffffu, mx, 1));
        mx = fmaxf(mx, __shfl_xor_sync(0xffffffffu, mx, 2));
        float sum = 0.0f;
        #pragma unroll 8
        for (int c = cb; c < cb + 48; c++) {
            float e = (c >= lo && c < hi) ? __expf(srow[c] - mx) : 0.0f;
            srow[c] = e;
            sum += e;
        }
        sum += __shfl_xor_sync(0xffffffffu, sum, 1);
        sum += __shfl_xor_sync(0xffffffffu, sum, 2);
        float inv = 1.0f / sum;
        __syncthreads();   // everyone done reading sQ/sK? (wmma reads finished pre-softmax sync)
        __nv_bfloat16* prow = sP + r * LDS_P;
        #pragma unroll 8
        for (int c = cb; c < cb + 48; c++)
            prow[c] = __float2bfloat16(srow[c] * inv);
    }
    __syncthreads();

    // O = P @ V : 64x64
    {
        int r0 = (warp & 3) * 16;
        int c0 = (warp >> 2) * 32;
        #pragma unroll
        for (int j = 0; j < 2; j++) {
            wmma::fragment<wmma::accumulator, 16, 16, 16, float> acc;
            wmma::fill_fragment(acc, 0.0f);
            #pragma unroll
            for (int kk = 0; kk < 12; kk++) {
                wmma::fragment<wmma::matrix_a, 16, 16, 16, __nv_bfloat16, wmma::row_major> afr;
                wmma::fragment<wmma::matrix_b, 16, 16, 16, __nv_bfloat16, wmma::row_major> bfr;
                wmma::load_matrix_sync(afr, sP + r0 * LDS_P + kk * 16, LDS_P);
                wmma::load_matrix_sync(bfr, sV + (kk * 16) * LDQ + c0 + j * 16, LDQ);
                wmma::mma_sync(acc, afr, bfr, acc);
            }
            wmma::store_matrix_sync(sO + r0 * LDQ + c0 + j * 16, acc, LDQ, wmma::mem_row_major);
        }
    }
    __syncthreads();

    #pragma unroll 4
    for (int e = tid; e < 64 * 64; e += 256) {
        int r = e >> 6, c = e & 63;
        attn_out[(tbase + r) * 512 + head * 64 + c] = __float2bfloat16(sO[r * LDQ + c]);
    }
}

// ---------------- host launcher ----------------
extern "C" void kernel_launch(void* const* d_in, const int* in_sizes, int n_in,
                              void* d_out, int out_size) {
    (void)in_sizes; (void)n_in; (void)out_size;
    const float* x       = (const float*)d_in[0];
    const float* ln_q_g  = (const float*)d_in[1];
    const float* ln_q_b  = (const float*)d_in[2];
    const float* ln_kv_g = (const float*)d_in[3];
    const float* ln_kv_b = (const float*)d_in[4];
    const float* W_kv    = (const float*)d_in[5];
    const float* b_kv    = (const float*)d_in[6];
    const float* W_o     = (const float*)d_in[7];
    const float* b_o     = (const float*)d_in[8];
    const float* gamma   = (const float*)d_in[9];
    const float* ln_m_g  = (const float*)d_in[10];
    const float* ln_m_b  = (const float*)d_in[11];
    const float* W_emb   = (const float*)d_in[12];
    const float* b_emb   = (const float*)d_in[13];
    const float* W1      = (const float*)d_in[14];
    const float* b1      = (const float*)d_in[15];
    const float* W2      = (const float*)d_in[16];
    const float* b2      = (const float*)d_in[17];
    const float* gamma_mlp = (const float*)d_in[18];
    float* out = (float*)d_out;

    void *p_q, *p_akv, *p_kv, *p_attn, *p_x1, *p_h0, *p_h1;
    void *p_wkv, *p_wo, *p_wemb, *p_w1, *p_w2;
    cudaGetSymbolAddress(&p_q,    g_q);
    cudaGetSymbolAddress(&p_akv,  g_akv);
    cudaGetSymbolAddress(&p_kv,   g_kv);
    cudaGetSymbolAddress(&p_attn, g_attn);
    cudaGetSymbolAddress(&p_x1,   g_x1);
    cudaGetSymbolAddress(&p_h0,   g_h0);
    cudaGetSymbolAddress(&p_h1,   g_h1);
    cudaGetSymbolAddress(&p_wkv,  g_wkv);
    cudaGetSymbolAddress(&p_wo,   g_wo);
    cudaGetSymbolAddress(&p_wemb, g_wemb);
    cudaGetSymbolAddress(&p_w1,   g_w1);
    cudaGetSymbolAddress(&p_w2,   g_w2);

    cudaFuncSetAttribute(attn_kernel, cudaFuncAttributeMaxDynamicSharedMemorySize, ATTN_SMEM);
    cudaFuncSetAttribute(gemm2<512,  EPI_BIAS_BF16>, cudaFuncAttributeMaxDynamicSharedMemorySize, GEMM_SMEM);
    cudaFuncSetAttribute(gemm2<512,  EPI_GELU_BF16>, cudaFuncAttributeMaxDynamicSharedMemorySize, GEMM_SMEM);
    cudaFuncSetAttribute(gemm2<512,  EPI_RESID_F32>, cudaFuncAttributeMaxDynamicSharedMemorySize, GEMM_SMEM);
    cudaFuncSetAttribute(gemm2<1024, EPI_RESID_F32>, cudaFuncAttributeMaxDynamicSharedMemorySize, GEMM_SMEM);

    // 0) weight convert+transpose (one launch, 5 segments)
    conv_w_all<<<dim3(2048, 5), 256>>>(W_kv,  (__nv_bfloat16*)p_wkv,
                                       W_o,   (__nv_bfloat16*)p_wo,
                                       W_emb, (__nv_bfloat16*)p_wemb,
                                       W1,    (__nv_bfloat16*)p_w1,
                                       W2,    (__nv_bfloat16*)p_w2);

    // 1) dual LN
    ln_kernel<<<NTOKS, 128>>>(x, ln_q_g, ln_q_b, (__nv_bfloat16*)p_q,
                                 ln_kv_g, ln_kv_b, (__nv_bfloat16*)p_akv);

    // 2) kv = akv @ W_kv + b_kv   [65536 x 1024]
    gemm2<512, EPI_BIAS_BF16><<<dim3(1024 / BN2, NTOKS / BM2), 256, GEMM_SMEM>>>(
        (const __nv_bfloat16*)p_akv, (const __nv_bfloat16*)p_wkv, b_kv,
        (__nv_bfloat16*)p_kv, nullptr, nullptr, nullptr, 1024);

    // 3) windowed attention
    attn_kernel<<<NGROUPS * SWIN * HEADS, 256, ATTN_SMEM>>>(
        (const __nv_bfloat16*)p_q, (const __nv_bfloat16*)p_kv, (__nv_bfloat16*)p_attn);

    // 4) x1 = x + gamma * (attn @ W_o + b_o)
    gemm2<512, EPI_RESID_F32><<<dim3(512 / BN2, NTOKS / BM2), 256, GEMM_SMEM>>>(
        (const __nv_bfloat16*)p_attn, (const __nv_bfloat16*)p_wo, b_o,
        nullptr, (float*)p_x1, x, gamma, 512);

    // 5) aemb = LN_m(x1)
    ln_kernel<<<NTOKS, 128>>>((const float*)p_x1, ln_m_g, ln_m_b, (__nv_bfloat16*)p_akv,
                              nullptr, nullptr, nullptr);

    // 6) h0 = aemb @ W_emb + b_emb
    gemm2<512, EPI_BIAS_BF16><<<dim3(512 / BN2, NTOKS / BM2), 256, GEMM_SMEM>>>(
        (const __nv_bfloat16*)p_akv, (const __nv_bfloat16*)p_wemb, b_emb,
        (__nv_bfloat16*)p_h0, nullptr, nullptr, nullptr, 512);

    // 7) h1 = gelu(h0 @ W1 + b1)
    gemm2<512, EPI_GELU_BF16><<<dim3(1024 / BN2, NTOKS / BM2), 256, GEMM_SMEM>>>(
        (const __nv_bfloat16*)p_h0, (const __nv_bfloat16*)p_w1, b1,
        (__nv_bfloat16*)p_h1, nullptr, nullptr, nullptr, 1024);

    // 8) out = x1 + gamma_mlp * (h1 @ W2 + b2)
    gemm2<1024, EPI_RESID_F32><<<dim3(512 / BN2, NTOKS / BM2), 256, GEMM_SMEM>>>(
        (const __nv_bfloat16*)p_h1, (const __nv_bfloat16*)p_w2, b2,
        nullptr, out, (const float*)p_x1, gamma_mlp, 512);
}